// round 2
// baseline (speedup 1.0000x reference)
#include <cuda_runtime.h>
#include <cuda_bf16.h>
#include <math.h>

// Problem constants (fixed shapes from reference)
#define BSZ   4
#define NSEQ  8192
#define DMODEL 1024
#define DI    2048
#define MROWS (BSZ * NSEQ)          // 32768
#define NCH   64                    // scan chunks
#define LCH   (NSEQ / NCH)          // 128 steps per chunk

// ---------------- scratch (device globals; no cudaMalloc allowed) ----------
__device__ float g_rrms[MROWS];                       // 128 KB
__device__ float g_a[(size_t)MROWS * DI];             // 256 MB  sigmoid gate
__device__ float g_b[(size_t)MROWS * DI];             // 256 MB  silu input
__device__ float g_h[(size_t)MROWS * DI];             // 256 MB  scan output
__device__ float g_aggA[NCH * BSZ * DI];              // 2 MB
__device__ float g_aggB[NCH * BSZ * DI];              // 2 MB
__device__ float g_hstart[NCH * BSZ * DI];            // 2 MB

// ---------------- rmsnorm scale per row ------------------------------------
__global__ void rms_kernel(const float* __restrict__ X) {
    int m = blockIdx.x;
    int tid = threadIdx.x;                    // 256 threads, 1024 floats/row
    const float4* xr = (const float4*)(X + (size_t)m * DMODEL);
    float4 v = xr[tid];
    float s = v.x * v.x + v.y * v.y + v.z * v.z + v.w * v.w;
    #pragma unroll
    for (int o = 16; o; o >>= 1) s += __shfl_xor_sync(0xffffffffu, s, o);
    __shared__ float ws[8];
    if ((tid & 31) == 0) ws[tid >> 5] = s;
    __syncthreads();
    if (tid < 8) {
        float t = ws[tid];
        #pragma unroll
        for (int o = 4; o; o >>= 1) t += __shfl_xor_sync(0xffu, t, o);
        if (tid == 0) g_rrms[m] = rsqrtf(t * (1.0f / DMODEL) + 1e-6f);
    }
}

// ---------------- GEMM1: ab = (x * rrms * norm_w) @ W_in^T, gate epilogue --
// A: x [M,1024] scaled; B: W_in [4096,1024] (K-major). C tile 128x128, K-tile 8.
__global__ __launch_bounds__(256) void gemm1_kernel(
    const float* __restrict__ X, const float* __restrict__ W,
    const float* __restrict__ bias, const float* __restrict__ nw)
{
    const int K = DMODEL;
    __shared__ float As[8][128];
    __shared__ float Bs[8][128];
    int tid = threadIdx.x;
    int m0 = blockIdx.y * 128, n0 = blockIdx.x * 128;
    int lrow = tid >> 1;
    int lcol = (tid & 1) * 4;
    int tx = tid & 15, ty = tid >> 4;

    const float* Aptr = X + (size_t)(m0 + lrow) * K + lcol;
    const float* Bptr = W + (size_t)(n0 + lrow) * K + lcol;
    float rr = g_rrms[m0 + lrow];

    float acc[8][8];
    #pragma unroll
    for (int i = 0; i < 8; i++)
        #pragma unroll
        for (int j = 0; j < 8; j++) acc[i][j] = 0.f;

    for (int k0 = 0; k0 < K; k0 += 8) {
        float4 av = *(const float4*)(Aptr + k0);
        float4 wv = *(const float4*)(nw + k0 + lcol);
        float4 bv = *(const float4*)(Bptr + k0);
        As[lcol + 0][lrow] = av.x * rr * wv.x;
        As[lcol + 1][lrow] = av.y * rr * wv.y;
        As[lcol + 2][lrow] = av.z * rr * wv.z;
        As[lcol + 3][lrow] = av.w * rr * wv.w;
        Bs[lcol + 0][lrow] = bv.x;
        Bs[lcol + 1][lrow] = bv.y;
        Bs[lcol + 2][lrow] = bv.z;
        Bs[lcol + 3][lrow] = bv.w;
        __syncthreads();
        #pragma unroll
        for (int kk = 0; kk < 8; kk++) {
            float4 a0 = *(const float4*)&As[kk][ty * 8];
            float4 a1 = *(const float4*)&As[kk][ty * 8 + 4];
            float4 b0 = *(const float4*)&Bs[kk][tx * 8];
            float4 b1 = *(const float4*)&Bs[kk][tx * 8 + 4];
            float af[8] = {a0.x, a0.y, a0.z, a0.w, a1.x, a1.y, a1.z, a1.w};
            float bf[8] = {b0.x, b0.y, b0.z, b0.w, b1.x, b1.y, b1.z, b1.w};
            #pragma unroll
            for (int i = 0; i < 8; i++)
                #pragma unroll
                for (int j = 0; j < 8; j++)
                    acc[i][j] = fmaf(af[i], bf[j], acc[i][j]);
        }
        __syncthreads();
    }

    // epilogue: cols [0,2048) -> sigmoid -> g_a ; cols [2048,4096) -> silu -> g_b
    #pragma unroll
    for (int i = 0; i < 8; i++) {
        int m = m0 + ty * 8 + i;
        #pragma unroll
        for (int j = 0; j < 8; j++) {
            int n = n0 + tx * 8 + j;
            float v = acc[i][j] + bias[n];
            float sg = 1.0f / (1.0f + __expf(-v));
            if (n < DI) g_a[(size_t)m * DI + n] = sg;
            else        g_b[(size_t)m * DI + (n - DI)] = v * sg;
        }
    }
}

// ---------------- scan pass 1: per-chunk aggregates (A = prod a, B = h@end|h0=0)
__global__ void scan_pass1() {
    int ch = blockIdx.x * 256 + threadIdx.x;
    int c  = blockIdx.y;
    int b  = blockIdx.z;
    size_t base = ((size_t)b * NSEQ + (size_t)c * LCH) * DI + ch;
    float A = 1.f, B = 0.f;
    #pragma unroll 4
    for (int i = 0; i < LCH; i++) {
        float av = g_a[base + (size_t)i * DI];
        float bv = g_b[base + (size_t)i * DI];
        B = fmaf(av, B, bv);
        A *= av;
    }
    int idx = (c * BSZ + b) * DI + ch;
    g_aggA[idx] = A;
    g_aggB[idx] = B;
}

// ---------------- scan pass 2: sequential over chunks -> carries at chunk starts
__global__ void scan_pass2(const float* __restrict__ hprev) {
    int t = blockIdx.x * 256 + threadIdx.x;   // 0..8191 == b*DI+ch
    float carry = hprev[t];
    int b = t / DI, ch = t % DI;
    for (int c = 0; c < NCH; c++) {
        int idx = (c * BSZ + b) * DI + ch;
        g_hstart[idx] = carry;
        carry = fmaf(g_aggA[idx], carry, g_aggB[idx]);
    }
}

// ---------------- scan pass 3: replay with carry, write h (+ h_last) -------
__global__ void scan_pass3(float* __restrict__ hlast) {
    int ch = blockIdx.x * 256 + threadIdx.x;
    int c  = blockIdx.y;
    int b  = blockIdx.z;
    float carry = g_hstart[(c * BSZ + b) * DI + ch];
    size_t base = ((size_t)b * NSEQ + (size_t)c * LCH) * DI + ch;
    #pragma unroll 4
    for (int i = 0; i < LCH; i++) {
        float av = g_a[base + (size_t)i * DI];
        float bv = g_b[base + (size_t)i * DI];
        carry = fmaf(av, carry, bv);
        g_h[base + (size_t)i * DI] = carry;
    }
    if (c == NCH - 1 && hlast) hlast[b * DI + ch] = carry;
}

// ---------------- GEMM2: out = h @ W_out^T + b_out + x ---------------------
__global__ __launch_bounds__(256) void gemm2_kernel(
    const float* __restrict__ W, const float* __restrict__ bias,
    const float* __restrict__ X, float* __restrict__ Out)
{
    const int K = DI;
    __shared__ float As[8][128];
    __shared__ float Bs[8][128];
    int tid = threadIdx.x;
    int m0 = blockIdx.y * 128, n0 = blockIdx.x * 128;
    int lrow = tid >> 1;
    int lcol = (tid & 1) * 4;
    int tx = tid & 15, ty = tid >> 4;

    const float* Aptr = g_h + (size_t)(m0 + lrow) * K + lcol;
    const float* Bptr = W + (size_t)(n0 + lrow) * K + lcol;

    float acc[8][8];
    #pragma unroll
    for (int i = 0; i < 8; i++)
        #pragma unroll
        for (int j = 0; j < 8; j++) acc[i][j] = 0.f;

    for (int k0 = 0; k0 < K; k0 += 8) {
        float4 av = *(const float4*)(Aptr + k0);
        float4 bv = *(const float4*)(Bptr + k0);
        As[lcol + 0][lrow] = av.x;
        As[lcol + 1][lrow] = av.y;
        As[lcol + 2][lrow] = av.z;
        As[lcol + 3][lrow] = av.w;
        Bs[lcol + 0][lrow] = bv.x;
        Bs[lcol + 1][lrow] = bv.y;
        Bs[lcol + 2][lrow] = bv.z;
        Bs[lcol + 3][lrow] = bv.w;
        __syncthreads();
        #pragma unroll
        for (int kk = 0; kk < 8; kk++) {
            float4 a0 = *(const float4*)&As[kk][ty * 8];
            float4 a1 = *(const float4*)&As[kk][ty * 8 + 4];
            float4 b0 = *(const float4*)&Bs[kk][tx * 8];
            float4 b1 = *(const float4*)&Bs[kk][tx * 8 + 4];
            float af[8] = {a0.x, a0.y, a0.z, a0.w, a1.x, a1.y, a1.z, a1.w};
            float bf[8] = {b0.x, b0.y, b0.z, b0.w, b1.x, b1.y, b1.z, b1.w};
            #pragma unroll
            for (int i = 0; i < 8; i++)
                #pragma unroll
                for (int j = 0; j < 8; j++)
                    acc[i][j] = fmaf(af[i], bf[j], acc[i][j]);
        }
        __syncthreads();
    }

    #pragma unroll
    for (int i = 0; i < 8; i++) {
        int m = m0 + ty * 8 + i;
        #pragma unroll
        for (int j = 0; j < 8; j++) {
            int n = n0 + tx * 8 + j;
            Out[(size_t)m * DMODEL + n] =
                acc[i][j] + bias[n] + X[(size_t)m * DMODEL + n];
        }
    }
}

// ---------------- launch ----------------------------------------------------
extern "C" void kernel_launch(void* const* d_in, const int* in_sizes, int n_in,
                              void* d_out, int out_size) {
    const float* x      = (const float*)d_in[0];   // (4, 8192, 1024)
    const float* h_prev = (const float*)d_in[1];   // (4, 2048)
    const float* norm_w = (const float*)d_in[2];   // (1024,)
    const float* W_in   = (const float*)d_in[3];   // (4096, 1024)
    const float* b_in   = (const float*)d_in[4];   // (4096,)
    const float* W_out  = (const float*)d_in[5];   // (1024, 2048)
    const float* b_out  = (const float*)d_in[6];   // (1024,)

    float* out = (float*)d_out;
    const size_t out_elems = (size_t)MROWS * DMODEL;          // 33,554,432
    float* hlast = (out_size >= (int)(out_elems + BSZ * DI))
                       ? out + out_elems : nullptr;

    rms_kernel<<<MROWS, 256>>>(x);
    gemm1_kernel<<<dim3(4096 / 128, MROWS / 128), 256>>>(x, W_in, b_in, norm_w);
    scan_pass1<<<dim3(DI / 256, NCH, BSZ), 256>>>();
    scan_pass2<<<(BSZ * DI) / 256, 256>>>(h_prev);
    scan_pass3<<<dim3(DI / 256, NCH, BSZ), 256>>>(hlast);
    gemm2_kernel<<<dim3(DMODEL / 128, MROWS / 128), 256>>>(W_out, b_out, x, out);
}

// round 11
// speedup vs baseline: 1.8626x; 1.8626x over previous
#include <cuda_runtime.h>
#include <cuda_bf16.h>
#include <math.h>
#include <stdint.h>

// Problem constants (fixed shapes from reference)
#define BSZ    4
#define NSEQ   8192
#define DMODEL 1024
#define DI     2048
#define MROWS  (BSZ * NSEQ)          // 32768
#define NCH    64                    // scan chunks
#define LCH    (NSEQ / NCH)          // 128 steps per chunk

// ---------------- scratch (device globals; no cudaMalloc allowed) ----------
__device__ float g_rrms[MROWS];                       // 128 KB
__device__ float g_a[(size_t)MROWS * DI];             // 256 MB  sigmoid gate
__device__ float g_b[(size_t)MROWS * DI];             // 256 MB  silu value
__device__ float g_h[(size_t)MROWS * DI];             // 256 MB  scan output
__device__ float g_aggA[NCH * BSZ * DI];              // 2 MB
__device__ float g_aggB[NCH * BSZ * DI];              // 2 MB
__device__ float g_hstart[NCH * BSZ * DI];            // 2 MB

// ================= helpers ==================================================
__device__ __forceinline__ uint32_t smem_u32(const void* p) {
    uint32_t a;
    asm("{ .reg .u64 t; cvta.to.shared.u64 t, %1; cvt.u32.u64 %0, t; }"
        : "=r"(a) : "l"(p));
    return a;
}

__device__ __forceinline__ void ldsm_x4(uint32_t addr, uint32_t* r) {
    asm volatile("ldmatrix.sync.aligned.m8n8.x4.shared.b16 {%0,%1,%2,%3}, [%4];"
                 : "=r"(r[0]), "=r"(r[1]), "=r"(r[2]), "=r"(r[3]) : "r"(addr));
}

__device__ __forceinline__ void mma_bf16(float* c, const uint32_t* a,
                                         uint32_t b0, uint32_t b1) {
    asm volatile(
        "mma.sync.aligned.m16n8k16.row.col.f32.bf16.bf16.f32 "
        "{%0,%1,%2,%3}, {%4,%5,%6,%7}, {%8,%9}, {%0,%1,%2,%3};"
        : "+f"(c[0]), "+f"(c[1]), "+f"(c[2]), "+f"(c[3])
        : "r"(a[0]), "r"(a[1]), "r"(a[2]), "r"(a[3]), "r"(b0), "r"(b1));
}

__device__ __forceinline__ uint32_t pack_bf2(__nv_bfloat16 a, __nv_bfloat16 b) {
    __nv_bfloat162 t = __halves2bfloat162(a, b);
    return *reinterpret_cast<uint32_t*>(&t);
}

// split float4 into hi/lo bf16 pairs and store (8B each) to shared
__device__ __forceinline__ void split_store(uint32_t hi_addr, uint32_t lo_addr,
                                            float4 v) {
    __nv_bfloat16 h0 = __float2bfloat16(v.x);
    __nv_bfloat16 h1 = __float2bfloat16(v.y);
    __nv_bfloat16 h2 = __float2bfloat16(v.z);
    __nv_bfloat16 h3 = __float2bfloat16(v.w);
    __nv_bfloat16 l0 = __float2bfloat16(v.x - __bfloat162float(h0));
    __nv_bfloat16 l1 = __float2bfloat16(v.y - __bfloat162float(h1));
    __nv_bfloat16 l2 = __float2bfloat16(v.z - __bfloat162float(h2));
    __nv_bfloat16 l3 = __float2bfloat16(v.w - __bfloat162float(h3));
    uint32_t hw0 = pack_bf2(h0, h1), hw1 = pack_bf2(h2, h3);
    uint32_t lw0 = pack_bf2(l0, l1), lw1 = pack_bf2(l2, l3);
    asm volatile("st.shared.v2.b32 [%0], {%1,%2};"
                 :: "r"(hi_addr), "r"(hw0), "r"(hw1) : "memory");
    asm volatile("st.shared.v2.b32 [%0], {%1,%2};"
                 :: "r"(lo_addr), "r"(lw0), "r"(lw1) : "memory");
}

// ---------------- rmsnorm scale per row ------------------------------------
__global__ void rms_kernel(const float* __restrict__ X) {
    int m = blockIdx.x;
    int tid = threadIdx.x;                    // 256 threads, 1024 floats/row
    const float4* xr = (const float4*)(X + (size_t)m * DMODEL);
    float4 v = xr[tid];
    float s = v.x * v.x + v.y * v.y + v.z * v.z + v.w * v.w;
    #pragma unroll
    for (int o = 16; o; o >>= 1) s += __shfl_xor_sync(0xffffffffu, s, o);
    __shared__ float ws[8];
    if ((tid & 31) == 0) ws[tid >> 5] = s;
    __syncthreads();
    if (tid < 8) {
        float t = ws[tid];
        #pragma unroll
        for (int o = 4; o; o >>= 1) t += __shfl_xor_sync(0xffu, t, o);
        if (tid == 0) g_rrms[m] = rsqrtf(t * (1.0f / DMODEL) + 1e-6f);
    }
}

// ================== bf16 split-precision GEMM (mma.sync) ====================
// C[128,128] tile; A [M,K] row-major fp32, B [N,K] row-major fp32 (B^T col).
// 8 warps in a 4(M) x 2(N) grid: warp owns 32(M) x 64(N).
#define PADK 40                       // bf16 elems per smem row (32 + 8 pad) = 80 B
#define SMB  (128 * PADK)             // elems per buffer

// EPI: 0 = gate epilogue (g_a/g_b), 1 = out = c + bias + X residual
// SRC_GH: A source is the device-global g_h (ignore Asrc parameter)
template <int EPI, bool SCALED, bool SRC_GH>
__global__ __launch_bounds__(256) void gemm_bf16_tc(
    const float* __restrict__ Asrc, const float* __restrict__ Bsrc,
    const float* __restrict__ bias, const float* __restrict__ nw,
    const float* __restrict__ Xres, float* __restrict__ Out, int K)
{
    __shared__ __align__(16) __nv_bfloat16 sAhi[SMB];
    __shared__ __align__(16) __nv_bfloat16 sAlo[SMB];
    __shared__ __align__(16) __nv_bfloat16 sBhi[SMB];
    __shared__ __align__(16) __nv_bfloat16 sBlo[SMB];

    const float* __restrict__ Ap = SRC_GH ? (const float*)g_h : Asrc;

    int tid = threadIdx.x, wid = tid >> 5, lane = tid & 31;
    int wm = wid & 3;            // 0..3 : rows [wm*32, wm*32+32)
    int wn = wid >> 2;           // 0..1 : cols [wn*64, wn*64+64)
    int m0 = blockIdx.y * 128, n0 = blockIdx.x * 128;

    uint32_t aHi = smem_u32(sAhi), aLo = smem_u32(sAlo);
    uint32_t bHi = smem_u32(sBhi), bLo = smem_u32(sBlo);

    // loader indexing: pos = tid + i*256 ; row = pos>>3 ; c = pos&7 (float4 col)
    float4 pa[4], pb[4];
    float rrms_c[4];
    #pragma unroll
    for (int i = 0; i < 4; i++) {
        int pos = tid + i * 256;
        int row = pos >> 3, c = pos & 7;
        pa[i] = *(const float4*)(Ap + (size_t)(m0 + row) * K + c * 4);
        pb[i] = *(const float4*)(Bsrc + (size_t)(n0 + row) * K + c * 4);
        if (SCALED) rrms_c[i] = g_rrms[m0 + row];
    }

    float acc[2][8][4];
    #pragma unroll
    for (int i = 0; i < 2; i++)
        #pragma unroll
        for (int j = 0; j < 8; j++)
            #pragma unroll
            for (int t = 0; t < 4; t++) acc[i][j][t] = 0.f;

    const int NCK = K / 32;
    for (int ck = 0; ck < NCK; ck++) {
        // convert + store staged chunk
        #pragma unroll
        for (int i = 0; i < 4; i++) {
            int pos = tid + i * 256;
            int row = pos >> 3, c = pos & 7;
            uint32_t off = (uint32_t)(row * 80 + c * 8);
            float4 va = pa[i];
            if (SCALED) {
                float rr = rrms_c[i];
                float4 w = *(const float4*)(nw + ck * 32 + c * 4);
                va.x *= rr * w.x; va.y *= rr * w.y;
                va.z *= rr * w.z; va.w *= rr * w.w;
            }
            split_store(aHi + off, aLo + off, va);
            split_store(bHi + off, bLo + off, pb[i]);
        }
        __syncthreads();
        // prefetch next chunk into registers (overlaps with MMA below)
        if (ck + 1 < NCK) {
            int k0 = (ck + 1) * 32;
            #pragma unroll
            for (int i = 0; i < 4; i++) {
                int pos = tid + i * 256;
                int row = pos >> 3, c = pos & 7;
                pa[i] = *(const float4*)(Ap + (size_t)(m0 + row) * K + k0 + c * 4);
                pb[i] = *(const float4*)(Bsrc + (size_t)(n0 + row) * K + k0 + c * 4);
            }
        }
        // 2 k16 steps
        #pragma unroll
        for (int ks = 0; ks < 2; ks++) {
            uint32_t koff = (uint32_t)(ks * 32 + (lane >> 4) * 16);  // bytes
            // A fragments: 2 m16 tiles, hi & lo
            uint32_t afh[2][4], afl[2][4];
            #pragma unroll
            for (int mt = 0; mt < 2; mt++) {
                uint32_t ro = (uint32_t)((wm * 32 + mt * 16 + (lane & 15)) * 80) + koff;
                ldsm_x4(aHi + ro, afh[mt]);
                ldsm_x4(aLo + ro, afl[mt]);
            }
            // B: 4 n16 groups per warp (WN=64)
            #pragma unroll
            for (int g = 0; g < 4; g++) {
                uint32_t ro = (uint32_t)((wn * 64 + g * 16 + (lane & 15)) * 80) + koff;
                uint32_t bfh[4], bfl[4];
                ldsm_x4(bHi + ro, bfh);
                ldsm_x4(bLo + ro, bfl);
                #pragma unroll
                for (int mt = 0; mt < 2; mt++) {
                    // tile nt = g*2 uses {b0,b2}; nt = g*2+1 uses {b1,b3}
                    mma_bf16(acc[mt][g * 2],     afh[mt], bfh[0], bfh[2]);
                    mma_bf16(acc[mt][g * 2],     afh[mt], bfl[0], bfl[2]);
                    mma_bf16(acc[mt][g * 2],     afl[mt], bfh[0], bfh[2]);
                    mma_bf16(acc[mt][g * 2 + 1], afh[mt], bfh[1], bfh[3]);
                    mma_bf16(acc[mt][g * 2 + 1], afh[mt], bfl[1], bfl[3]);
                    mma_bf16(acc[mt][g * 2 + 1], afl[mt], bfh[1], bfh[3]);
                }
            }
        }
        __syncthreads();
    }

    // ---------------- epilogue ----------------
    int lr = lane >> 2, lc = (lane & 3) * 2;
    #pragma unroll
    for (int mt = 0; mt < 2; mt++) {
        #pragma unroll
        for (int nt = 0; nt < 8; nt++) {
            int n = n0 + wn * 64 + nt * 8 + lc;
            float b0 = bias[n], b1 = bias[n + 1];
            #pragma unroll
            for (int half = 0; half < 2; half++) {
                int m = m0 + wm * 32 + mt * 16 + lr + half * 8;
                float c0 = acc[mt][nt][half * 2 + 0] + b0;
                float c1 = acc[mt][nt][half * 2 + 1] + b1;
                if (EPI == 0) {
                    float s0 = 1.0f / (1.0f + __expf(-c0));
                    float s1 = 1.0f / (1.0f + __expf(-c1));
                    if (n < DI) {
                        float2* d = (float2*)(g_a + (size_t)m * DI + n);
                        *d = make_float2(s0, s1);
                    } else {
                        float2* d = (float2*)(g_b + (size_t)m * DI + (n - DI));
                        *d = make_float2(c0 * s0, c1 * s1);
                    }
                } else {
                    const float* xr = Xres + (size_t)m * DMODEL + n;
                    float2* d = (float2*)(Out + (size_t)m * DMODEL + n);
                    *d = make_float2(c0 + xr[0], c1 + xr[1]);
                }
            }
        }
    }
}

// ---------------- scan pass 1: per-chunk aggregates ------------------------
__global__ void scan_pass1() {
    int ch = blockIdx.x * 256 + threadIdx.x;
    int c  = blockIdx.y;
    int b  = blockIdx.z;
    size_t base = ((size_t)b * NSEQ + (size_t)c * LCH) * DI + ch;
    float A = 1.f, B = 0.f;
    #pragma unroll 4
    for (int i = 0; i < LCH; i++) {
        float av = g_a[base + (size_t)i * DI];
        float bv = g_b[base + (size_t)i * DI];
        B = fmaf(av, B, bv);
        A *= av;
    }
    int idx = (c * BSZ + b) * DI + ch;
    g_aggA[idx] = A;
    g_aggB[idx] = B;
}

// ---------------- scan pass 2: sequential over chunks ----------------------
__global__ void scan_pass2(const float* __restrict__ hprev) {
    int t = blockIdx.x * 256 + threadIdx.x;   // 0..8191 == b*DI+ch
    float carry = hprev[t];
    int b = t / DI, ch = t % DI;
    for (int c = 0; c < NCH; c++) {
        int idx = (c * BSZ + b) * DI + ch;
        g_hstart[idx] = carry;
        carry = fmaf(g_aggA[idx], carry, g_aggB[idx]);
    }
}

// ---------------- scan pass 3: replay with carry ---------------------------
__global__ void scan_pass3(float* __restrict__ hlast) {
    int ch = blockIdx.x * 256 + threadIdx.x;
    int c  = blockIdx.y;
    int b  = blockIdx.z;
    float carry = g_hstart[(c * BSZ + b) * DI + ch];
    size_t base = ((size_t)b * NSEQ + (size_t)c * LCH) * DI + ch;
    #pragma unroll 4
    for (int i = 0; i < LCH; i++) {
        float av = g_a[base + (size_t)i * DI];
        float bv = g_b[base + (size_t)i * DI];
        carry = fmaf(av, carry, bv);
        g_h[base + (size_t)i * DI] = carry;
    }
    if (c == NCH - 1 && hlast) hlast[b * DI + ch] = carry;
}

// ---------------- launch ----------------------------------------------------
extern "C" void kernel_launch(void* const* d_in, const int* in_sizes, int n_in,
                              void* d_out, int out_size) {
    const float* x      = (const float*)d_in[0];   // (4, 8192, 1024)
    const float* h_prev = (const float*)d_in[1];   // (4, 2048)
    const float* norm_w = (const float*)d_in[2];   // (1024,)
    const float* W_in   = (const float*)d_in[3];   // (4096, 1024)
    const float* b_in   = (const float*)d_in[4];   // (4096,)
    const float* W_out  = (const float*)d_in[5];   // (1024, 2048)
    const float* b_out  = (const float*)d_in[6];   // (1024,)

    float* out = (float*)d_out;
    const size_t out_elems = (size_t)MROWS * DMODEL;          // 33,554,432
    float* hlast = (out_size >= (int)(out_elems + BSZ * DI))
                       ? out + out_elems : nullptr;

    rms_kernel<<<MROWS, 256>>>(x);
    // GEMM1: [32768 x 4096] = xn @ W_in^T, gate epilogue
    gemm_bf16_tc<0, true, false><<<dim3((2 * DI) / 128, MROWS / 128), 256>>>(
        x, W_in, b_in, norm_w, nullptr, nullptr, DMODEL);
    scan_pass1<<<dim3(DI / 256, NCH, BSZ), 256>>>();
    scan_pass2<<<(BSZ * DI) / 256, 256>>>(h_prev);
    scan_pass3<<<dim3(DI / 256, NCH, BSZ), 256>>>(hlast);
    // GEMM2: [32768 x 1024] = h @ W_out^T + b_out + x  (A source = g_h inside)
    gemm_bf16_tc<1, false, true><<<dim3(DMODEL / 128, MROWS / 128), 256>>>(
        nullptr, W_out, b_out, nullptr, x, out, DI);
}

// round 14
// speedup vs baseline: 2.5953x; 1.3934x over previous
#include <cuda_runtime.h>
#include <cuda_fp16.h>
#include <math.h>
#include <stdint.h>

// Problem constants (fixed shapes from reference)
#define BSZ    4
#define NSEQ   8192
#define DMODEL 1024
#define DI     2048
#define MROWS  (BSZ * NSEQ)          // 32768
#define NCH    64                    // scan chunks
#define LCH    (NSEQ / NCH)          // 128 steps per chunk

// ---------------- scratch (device globals; no cudaMalloc allowed) ----------
__device__ float g_rrms[MROWS];                       // 128 KB
__device__ float g_a[(size_t)MROWS * DI];             // 256 MB  sigmoid gate
__device__ float g_b[(size_t)MROWS * DI];             // 256 MB  silu value
__device__ float g_h[(size_t)MROWS * DI];             // 256 MB  scan output
__device__ float g_aggA[NCH * BSZ * DI];              // 2 MB
__device__ float g_aggB[NCH * BSZ * DI];              // 2 MB
__device__ float g_hstart[NCH * BSZ * DI];            // 2 MB
__device__ __half g_Wih[(size_t)(2 * DI) * DMODEL];   // 8 MB  fp16 W_in
__device__ __half g_Woh[(size_t)DMODEL * DI];         // 4 MB  fp16 W_out

// ================= helpers ==================================================
__device__ __forceinline__ uint32_t smem_u32(const void* p) {
    uint32_t a;
    asm("{ .reg .u64 t; cvta.to.shared.u64 t, %1; cvt.u32.u64 %0, t; }"
        : "=r"(a) : "l"(p));
    return a;
}

__device__ __forceinline__ void ldsm_x4(uint32_t addr, uint32_t* r) {
    asm volatile("ldmatrix.sync.aligned.m8n8.x4.shared.b16 {%0,%1,%2,%3}, [%4];"
                 : "=r"(r[0]), "=r"(r[1]), "=r"(r[2]), "=r"(r[3]) : "r"(addr));
}

__device__ __forceinline__ void mma_fp16(float* c, const uint32_t* a,
                                         uint32_t b0, uint32_t b1) {
    asm volatile(
        "mma.sync.aligned.m16n8k16.row.col.f32.f16.f16.f32 "
        "{%0,%1,%2,%3}, {%4,%5,%6,%7}, {%8,%9}, {%0,%1,%2,%3};"
        : "+f"(c[0]), "+f"(c[1]), "+f"(c[2]), "+f"(c[3])
        : "r"(a[0]), "r"(a[1]), "r"(a[2]), "r"(a[3]), "r"(b0), "r"(b1));
}

// split float4 into fp16 hi + fp16 lo residual, store 8B each to shared
__device__ __forceinline__ void split_store_h(uint32_t hi_addr, uint32_t lo_addr,
                                              float4 v) {
    __half h0 = __float2half_rn(v.x);
    __half h1 = __float2half_rn(v.y);
    __half h2 = __float2half_rn(v.z);
    __half h3 = __float2half_rn(v.w);
    __half2 hp0 = __halves2half2(h0, h1);
    __half2 hp1 = __halves2half2(h2, h3);
    __half2 lp0 = __floats2half2_rn(v.x - __half2float(h0), v.y - __half2float(h1));
    __half2 lp1 = __floats2half2_rn(v.z - __half2float(h2), v.w - __half2float(h3));
    uint32_t hw0 = *reinterpret_cast<uint32_t*>(&hp0);
    uint32_t hw1 = *reinterpret_cast<uint32_t*>(&hp1);
    uint32_t lw0 = *reinterpret_cast<uint32_t*>(&lp0);
    uint32_t lw1 = *reinterpret_cast<uint32_t*>(&lp1);
    asm volatile("st.shared.v2.b32 [%0], {%1,%2};"
                 :: "r"(hi_addr), "r"(hw0), "r"(hw1) : "memory");
    asm volatile("st.shared.v2.b32 [%0], {%1,%2};"
                 :: "r"(lo_addr), "r"(lw0), "r"(lw1) : "memory");
}

// ---------------- weight pre-convert fp32 -> fp16 --------------------------
__global__ void conv_w_kernel(const float* __restrict__ src,
                              __half* __restrict__ dst, int n4) {
    int i = blockIdx.x * 256 + threadIdx.x;
    if (i < n4) {
        float4 v = ((const float4*)src)[i];
        __half2 h0 = __floats2half2_rn(v.x, v.y);
        __half2 h1 = __floats2half2_rn(v.z, v.w);
        ((__half2*)dst)[i * 2]     = h0;
        ((__half2*)dst)[i * 2 + 1] = h1;
    }
}

// ---------------- rmsnorm scale per row ------------------------------------
__global__ void rms_kernel(const float* __restrict__ X) {
    int m = blockIdx.x;
    int tid = threadIdx.x;                    // 256 threads, 1024 floats/row
    const float4* xr = (const float4*)(X + (size_t)m * DMODEL);
    float4 v = xr[tid];
    float s = v.x * v.x + v.y * v.y + v.z * v.z + v.w * v.w;
    #pragma unroll
    for (int o = 16; o; o >>= 1) s += __shfl_xor_sync(0xffffffffu, s, o);
    __shared__ float ws[8];
    if ((tid & 31) == 0) ws[tid >> 5] = s;
    __syncthreads();
    if (tid < 8) {
        float t = ws[tid];
        #pragma unroll
        for (int o = 4; o; o >>= 1) t += __shfl_xor_sync(0xffu, t, o);
        if (tid == 0) g_rrms[m] = rsqrtf(t * (1.0f / DMODEL) + 1e-6f);
    }
}

// ============ fp16 2-term split GEMM (mma.sync m16n8k16) ====================
// C[128,128] tile; A [M,K] fp32 row-major (split hi/lo), B [N,K] fp16 row-major.
// D = Ahi*B + Alo*B  (B pre-rounded to fp16; Ahi*Blo term dropped by design).
// 8 warps in a 4(M) x 2(N) grid: warp owns 32(M) x 64(N).
#define PADK 40                       // fp16 elems per smem row (32 + 8 pad) = 80 B
#define SMB  (128 * PADK)             // elems per buffer

// EPI: 0 = gate epilogue (g_a/g_b), 1 = out = c + bias + X residual
// SRC_GH: A source is the device-global g_h (ignore Asrc parameter)
template <int EPI, bool SCALED, bool SRC_GH>
__global__ __launch_bounds__(256) void gemm_fp16_tc(
    const float* __restrict__ Asrc, const __half* __restrict__ Bh,
    const float* __restrict__ bias, const float* __restrict__ nw,
    const float* __restrict__ Xres, float* __restrict__ Out, int K)
{
    __shared__ __align__(16) __half sAhi[SMB];
    __shared__ __align__(16) __half sAlo[SMB];
    __shared__ __align__(16) __half sBhi[SMB];

    const float* __restrict__ Ap = SRC_GH ? (const float*)g_h : Asrc;

    int tid = threadIdx.x, wid = tid >> 5, lane = tid & 31;
    int wm = wid & 3;            // 0..3 : rows [wm*32, wm*32+32)
    int wn = wid >> 2;           // 0..1 : cols [wn*64, wn*64+64)
    int m0 = blockIdx.y * 128, n0 = blockIdx.x * 128;

    uint32_t aHi = smem_u32(sAhi), aLo = smem_u32(sAlo), bHi = smem_u32(sBhi);

    // A loader: 1024 float4 positions; pos = tid + i*256, row = pos>>3, c = pos&7
    // B loader: 512 uint4 positions (128 rows x 32 fp16); row = pos>>2, c = pos&3
    float4 pa[4];
    uint4  pbv[2];
    float rrms_c[4];
    #pragma unroll
    for (int i = 0; i < 4; i++) {
        int pos = tid + i * 256;
        int row = pos >> 3, c = pos & 7;
        pa[i] = *(const float4*)(Ap + (size_t)(m0 + row) * K + c * 4);
        if (SCALED) rrms_c[i] = g_rrms[m0 + row];
    }
    #pragma unroll
    for (int i = 0; i < 2; i++) {
        int pos = tid + i * 256;
        int row = pos >> 2, c = pos & 3;
        pbv[i] = *(const uint4*)(Bh + (size_t)(n0 + row) * K + c * 8);
    }

    float acc[2][8][4];
    #pragma unroll
    for (int i = 0; i < 2; i++)
        #pragma unroll
        for (int j = 0; j < 8; j++)
            #pragma unroll
            for (int t = 0; t < 4; t++) acc[i][j][t] = 0.f;

    const int NCK = K / 32;
    for (int ck = 0; ck < NCK; ck++) {
        // stage current chunk to smem
        #pragma unroll
        for (int i = 0; i < 4; i++) {
            int pos = tid + i * 256;
            int row = pos >> 3, c = pos & 7;
            uint32_t off = (uint32_t)(row * 80 + c * 8);
            float4 va = pa[i];
            if (SCALED) {
                float rr = rrms_c[i];
                float4 w = *(const float4*)(nw + ck * 32 + c * 4);
                va.x *= rr * w.x; va.y *= rr * w.y;
                va.z *= rr * w.z; va.w *= rr * w.w;
            }
            split_store_h(aHi + off, aLo + off, va);
        }
        #pragma unroll
        for (int i = 0; i < 2; i++) {
            int pos = tid + i * 256;
            int row = pos >> 2, c = pos & 3;
            uint32_t off = (uint32_t)(row * 80 + c * 16);
            asm volatile("st.shared.v4.b32 [%0], {%1,%2,%3,%4};"
                         :: "r"(bHi + off), "r"(pbv[i].x), "r"(pbv[i].y),
                            "r"(pbv[i].z), "r"(pbv[i].w) : "memory");
        }
        __syncthreads();
        // prefetch next chunk into registers (overlaps with MMA below)
        if (ck + 1 < NCK) {
            int k0 = (ck + 1) * 32;
            #pragma unroll
            for (int i = 0; i < 4; i++) {
                int pos = tid + i * 256;
                int row = pos >> 3, c = pos & 7;
                pa[i] = *(const float4*)(Ap + (size_t)(m0 + row) * K + k0 + c * 4);
            }
            #pragma unroll
            for (int i = 0; i < 2; i++) {
                int pos = tid + i * 256;
                int row = pos >> 2, c = pos & 3;
                pbv[i] = *(const uint4*)(Bh + (size_t)(n0 + row) * K + k0 + c * 8);
            }
        }
        // 2 k16 steps
        #pragma unroll
        for (int ks = 0; ks < 2; ks++) {
            uint32_t koff = (uint32_t)(ks * 32 + (lane >> 4) * 16);  // bytes
            uint32_t afh[2][4], afl[2][4];
            #pragma unroll
            for (int mt = 0; mt < 2; mt++) {
                uint32_t ro = (uint32_t)((wm * 32 + mt * 16 + (lane & 15)) * 80) + koff;
                ldsm_x4(aHi + ro, afh[mt]);
                ldsm_x4(aLo + ro, afl[mt]);
            }
            #pragma unroll
            for (int g = 0; g < 4; g++) {
                uint32_t ro = (uint32_t)((wn * 64 + g * 16 + (lane & 15)) * 80) + koff;
                uint32_t bf[4];
                ldsm_x4(bHi + ro, bf);
                #pragma unroll
                for (int mt = 0; mt < 2; mt++) {
                    // tile nt = g*2 uses {b0,b2}; nt = g*2+1 uses {b1,b3}
                    mma_fp16(acc[mt][g * 2],     afh[mt], bf[0], bf[2]);
                    mma_fp16(acc[mt][g * 2],     afl[mt], bf[0], bf[2]);
                    mma_fp16(acc[mt][g * 2 + 1], afh[mt], bf[1], bf[3]);
                    mma_fp16(acc[mt][g * 2 + 1], afl[mt], bf[1], bf[3]);
                }
            }
        }
        __syncthreads();
    }

    // ---------------- epilogue ----------------
    int lr = lane >> 2, lc = (lane & 3) * 2;
    #pragma unroll
    for (int mt = 0; mt < 2; mt++) {
        #pragma unroll
        for (int nt = 0; nt < 8; nt++) {
            int n = n0 + wn * 64 + nt * 8 + lc;
            float b0 = bias[n], b1 = bias[n + 1];
            #pragma unroll
            for (int half = 0; half < 2; half++) {
                int m = m0 + wm * 32 + mt * 16 + lr + half * 8;
                float c0 = acc[mt][nt][half * 2 + 0] + b0;
                float c1 = acc[mt][nt][half * 2 + 1] + b1;
                if (EPI == 0) {
                    float s0 = 1.0f / (1.0f + __expf(-c0));
                    float s1 = 1.0f / (1.0f + __expf(-c1));
                    if (n < DI) {
                        float2* d = (float2*)(g_a + (size_t)m * DI + n);
                        *d = make_float2(s0, s1);
                    } else {
                        float2* d = (float2*)(g_b + (size_t)m * DI + (n - DI));
                        *d = make_float2(c0 * s0, c1 * s1);
                    }
                } else {
                    const float* xr = Xres + (size_t)m * DMODEL + n;
                    float2* d = (float2*)(Out + (size_t)m * DMODEL + n);
                    *d = make_float2(c0 + xr[0], c1 + xr[1]);
                }
            }
        }
    }
}

// ---------------- scan pass 1: per-chunk aggregates ------------------------
__global__ void scan_pass1() {
    int ch = blockIdx.x * 256 + threadIdx.x;
    int c  = blockIdx.y;
    int b  = blockIdx.z;
    size_t base = ((size_t)b * NSEQ + (size_t)c * LCH) * DI + ch;
    float A = 1.f, B = 0.f;
    #pragma unroll 4
    for (int i = 0; i < LCH; i++) {
        float av = g_a[base + (size_t)i * DI];
        float bv = g_b[base + (size_t)i * DI];
        B = fmaf(av, B, bv);
        A *= av;
    }
    int idx = (c * BSZ + b) * DI + ch;
    g_aggA[idx] = A;
    g_aggB[idx] = B;
}

// ---------------- scan pass 2: sequential over chunks ----------------------
__global__ void scan_pass2(const float* __restrict__ hprev) {
    int t = blockIdx.x * 256 + threadIdx.x;   // 0..8191 == b*DI+ch
    float carry = hprev[t];
    int b = t / DI, ch = t % DI;
    for (int c = 0; c < NCH; c++) {
        int idx = (c * BSZ + b) * DI + ch;
        g_hstart[idx] = carry;
        carry = fmaf(g_aggA[idx], carry, g_aggB[idx]);
    }
}

// ---------------- scan pass 3: replay with carry ---------------------------
__global__ void scan_pass3(float* __restrict__ hlast) {
    int ch = blockIdx.x * 256 + threadIdx.x;
    int c  = blockIdx.y;
    int b  = blockIdx.z;
    float carry = g_hstart[(c * BSZ + b) * DI + ch];
    size_t base = ((size_t)b * NSEQ + (size_t)c * LCH) * DI + ch;
    #pragma unroll 4
    for (int i = 0; i < LCH; i++) {
        float av = g_a[base + (size_t)i * DI];
        float bv = g_b[base + (size_t)i * DI];
        carry = fmaf(av, carry, bv);
        g_h[base + (size_t)i * DI] = carry;
    }
    if (c == NCH - 1 && hlast) hlast[b * DI + ch] = carry;
}

// ---------------- weight convert wrapper kernels ----------------------------
__global__ void conv_win_kernel(const float* __restrict__ src) {
    int i = blockIdx.x * 256 + threadIdx.x;
    float4 v = ((const float4*)src)[i];
    __half2 h0 = __floats2half2_rn(v.x, v.y);
    __half2 h1 = __floats2half2_rn(v.z, v.w);
    ((__half2*)g_Wih)[i * 2]     = h0;
    ((__half2*)g_Wih)[i * 2 + 1] = h1;
}
__global__ void conv_wout_kernel(const float* __restrict__ src) {
    int i = blockIdx.x * 256 + threadIdx.x;
    float4 v = ((const float4*)src)[i];
    __half2 h0 = __floats2half2_rn(v.x, v.y);
    __half2 h1 = __floats2half2_rn(v.z, v.w);
    ((__half2*)g_Woh)[i * 2]     = h0;
    ((__half2*)g_Woh)[i * 2 + 1] = h1;
}

// ---------------- launch ----------------------------------------------------
extern "C" void kernel_launch(void* const* d_in, const int* in_sizes, int n_in,
                              void* d_out, int out_size) {
    const float* x      = (const float*)d_in[0];   // (4, 8192, 1024)
    const float* h_prev = (const float*)d_in[1];   // (4, 2048)
    const float* norm_w = (const float*)d_in[2];   // (1024,)
    const float* W_in   = (const float*)d_in[3];   // (4096, 1024)
    const float* b_in   = (const float*)d_in[4];   // (4096,)
    const float* W_out  = (const float*)d_in[5];   // (1024, 2048)
    const float* b_out  = (const float*)d_in[6];   // (1024,)

    float* out = (float*)d_out;
    const size_t out_elems = (size_t)MROWS * DMODEL;          // 33,554,432
    float* hlast = (out_size >= (int)(out_elems + BSZ * DI))
                       ? out + out_elems : nullptr;

    // get device pointers for fp16 weight buffers (B operand of GEMMs)
    // (device globals are directly addressable inside kernels; for the GEMM
    //  parameter we pass via a tiny lookup kernel-free trick: the GEMM reads
    //  the symbol only through the pointer we pass, so fetch addresses here)
    // NOTE: cudaGetSymbolAddress is host API, allowed (no allocation).
    static __half* wih_dev = nullptr;
    static __half* woh_dev = nullptr;
    if (!wih_dev) {
        void* p;
        cudaGetSymbolAddress(&p, g_Wih); wih_dev = (__half*)p;
        cudaGetSymbolAddress(&p, g_Woh); woh_dev = (__half*)p;
    }

    rms_kernel<<<MROWS, 256>>>(x);
    conv_win_kernel<<<(2 * DI) * DMODEL / 4 / 256, 256>>>(W_in);
    conv_wout_kernel<<<DMODEL * DI / 4 / 256, 256>>>(W_out);
    // GEMM1: [32768 x 4096] = xn @ W_in^T, gate epilogue
    gemm_fp16_tc<0, true, false><<<dim3((2 * DI) / 128, MROWS / 128), 256>>>(
        x, wih_dev, b_in, norm_w, nullptr, nullptr, DMODEL);
    scan_pass1<<<dim3(DI / 256, NCH, BSZ), 256>>>();
    scan_pass2<<<(BSZ * DI) / 256, 256>>>(h_prev);
    scan_pass3<<<dim3(DI / 256, NCH, BSZ), 256>>>(hlast);
    // GEMM2: [32768 x 1024] = h @ W_out^T + b_out + x  (A source = g_h inside)
    gemm_fp16_tc<1, false, true><<<dim3(DMODEL / 128, MROWS / 128), 256>>>(
        nullptr, woh_dev, b_out, nullptr, x, out, DI);
}